// round 1
// baseline (speedup 1.0000x reference)
#include <cuda_runtime.h>
#include <cstdint>

// Fused QKV projection, TF32 tensor-core GEMM:
//   X[16384,1024] @ [Wq|Wk|Wv][1024,3072] + bias, head-split epilogue.
// Output: q,k,v each [4,16,4096,64] fp32, concatenated in d_out.

#define MDIM   16384
#define KDIM   1024
#define NPM    1024      // N per matrix (q/k/v)
#define BM     128
#define BN     128
#define BK     32
#define AS_STRIDE 36     // BK + 4 pad (floats)
#define BS_STRIDE 136    // BN + 8 pad (floats)
#define A_SZ   (BM * AS_STRIDE)   // 4608 floats
#define B_SZ   (BK * BS_STRIDE)   // 4352 floats
#define STAGE_SZ (A_SZ + B_SZ)    // 8960 floats
#define SMEM_BYTES (STAGE_SZ * 2 * 4)   // 71680 B
#define OUT_PER_MAT (4 * 16 * 4096 * 64)  // 16777216

__device__ __forceinline__ uint32_t f2tf32(float x) {
    uint32_t r;
    asm("cvt.rna.tf32.f32 %0, %1;" : "=r"(r) : "f"(x));
    return r;
}

__device__ __forceinline__ void cp16(uint32_t dst_smem, const float* src) {
    asm volatile("cp.async.cg.shared.global [%0], [%1], 16;" :: "r"(dst_smem), "l"(src));
}

__device__ __forceinline__ void mma_tf32(float* c, const uint32_t* a, const uint32_t* b) {
    asm volatile(
        "mma.sync.aligned.m16n8k8.row.col.f32.tf32.tf32.f32 "
        "{%0,%1,%2,%3},{%4,%5,%6,%7},{%8,%9},{%0,%1,%2,%3};"
        : "+f"(c[0]), "+f"(c[1]), "+f"(c[2]), "+f"(c[3])
        : "r"(a[0]), "r"(a[1]), "r"(a[2]), "r"(a[3]),
          "r"(b[0]), "r"(b[1]));
}

__global__ void __launch_bounds__(256)
qkv_tf32_kernel(const float* __restrict__ X,
                const float* __restrict__ Wq, const float* __restrict__ bq,
                const float* __restrict__ Wk, const float* __restrict__ bk,
                const float* __restrict__ Wv, const float* __restrict__ bv,
                float* __restrict__ out)
{
    extern __shared__ float smem[];

    const int tid  = threadIdx.x;
    const int warp = tid >> 5;
    const int lane = tid & 31;
    const int g    = lane >> 2;   // groupID 0..7
    const int t    = lane & 3;    // threadID_in_group 0..3
    const int warpRow = warp >> 1;  // 0..3  (32 rows each)
    const int warpCol = warp & 1;   // 0..1  (64 cols each)

    const int nblk = blockIdx.x;    // 0..23
    const int mblk = blockIdx.y;    // 0..127
    const int mat  = nblk >> 3;     // 0=q,1=k,2=v
    const int n0   = (nblk & 7) * BN;   // column offset within the selected W
    const int m0   = mblk * BM;

    const float* W    = (mat == 0) ? Wq : (mat == 1) ? Wk : Wv;
    const float* bias = (mat == 0) ? bq : (mat == 1) ? bk : bv;

    const uint32_t smem_base = (uint32_t)__cvta_generic_to_shared(smem);

    float acc[2][8][4];
#pragma unroll
    for (int i = 0; i < 2; i++)
#pragma unroll
        for (int j = 0; j < 8; j++)
#pragma unroll
            for (int r = 0; r < 4; r++)
                acc[i][j][r] = 0.0f;

    // ---- async stage loader: A tile [BM x BK], B tile [BK x BN] ----
    auto load_stage = [&](int buf, int k0) {
        const uint32_t aBase = smem_base + (uint32_t)(buf * STAGE_SZ) * 4u;
        const uint32_t bBase = aBase + (uint32_t)A_SZ * 4u;
#pragma unroll
        for (int i = 0; i < 4; i++) {       // A: 128 rows x 8 float4
            int c   = tid + i * 256;
            int r   = c >> 3;
            int col = (c & 7) * 4;
            cp16(aBase + (uint32_t)(r * AS_STRIDE + col) * 4u,
                 X + (size_t)(m0 + r) * KDIM + k0 + col);
        }
#pragma unroll
        for (int i = 0; i < 4; i++) {       // B: 32 rows x 32 float4
            int c   = tid + i * 256;
            int r   = c >> 5;
            int col = (c & 31) * 4;
            cp16(bBase + (uint32_t)(r * BS_STRIDE + col) * 4u,
                 W + (size_t)(k0 + r) * NPM + n0 + col);
        }
        asm volatile("cp.async.commit_group;");
    };

    load_stage(0, 0);

    const int NK = KDIM / BK;   // 32
    for (int kt = 0; kt < NK; kt++) {
        if (kt + 1 < NK) {
            load_stage((kt + 1) & 1, (kt + 1) * BK);
            asm volatile("cp.async.wait_group 1;");
        } else {
            asm volatile("cp.async.wait_group 0;");
        }
        __syncthreads();

        const float* A  = smem + (kt & 1) * STAGE_SZ;
        const float* Bs = A + A_SZ;

#pragma unroll
        for (int ks = 0; ks < 4; ks++) {
            const int kk = ks * 8 + t;

            uint32_t afr[2][4];
#pragma unroll
            for (int mt = 0; mt < 2; mt++) {
                const int row = warpRow * 32 + mt * 16 + g;
                afr[mt][0] = f2tf32(A[ row      * AS_STRIDE + kk    ]);
                afr[mt][1] = f2tf32(A[(row + 8) * AS_STRIDE + kk    ]);
                afr[mt][2] = f2tf32(A[ row      * AS_STRIDE + kk + 4]);
                afr[mt][3] = f2tf32(A[(row + 8) * AS_STRIDE + kk + 4]);
            }

            uint32_t bfr[8][2];
#pragma unroll
            for (int nt = 0; nt < 8; nt++) {
                const int col = warpCol * 64 + nt * 8 + g;
                bfr[nt][0] = f2tf32(Bs[ kk      * BS_STRIDE + col]);
                bfr[nt][1] = f2tf32(Bs[(kk + 4) * BS_STRIDE + col]);
            }

#pragma unroll
            for (int mt = 0; mt < 2; mt++)
#pragma unroll
                for (int nt = 0; nt < 8; nt++)
                    mma_tf32(acc[mt][nt], afr[mt], bfr[nt]);
        }
        __syncthreads();
    }

    // ---- epilogue: bias add + head-split scatter ----
    float* outMat = out + (size_t)mat * OUT_PER_MAT;
#pragma unroll
    for (int mt = 0; mt < 2; mt++) {
#pragma unroll
        for (int rh = 0; rh < 2; rh++) {
            const int row = m0 + warpRow * 32 + mt * 16 + g + rh * 8;
            const int bb  = row >> 12;     // batch
            const int s   = row & 4095;    // seq
#pragma unroll
            for (int nt = 0; nt < 8; nt++) {
                const int nloc = n0 + warpCol * 64 + nt * 8 + 2 * t; // within [0,1024)
                const int head = nloc >> 6;
                const int d    = nloc & 63;
                const float v0 = acc[mt][nt][rh * 2 + 0] + bias[nloc];
                const float v1 = acc[mt][nt][rh * 2 + 1] + bias[nloc + 1];
                const size_t idx =
                    ((size_t)((bb * 16 + head) * 4096 + s)) * 64 + d;
                float2 val = make_float2(v0, v1);
                *reinterpret_cast<float2*>(outMat + idx) = val;
            }
        }
    }
}

extern "C" void kernel_launch(void* const* d_in, const int* in_sizes, int n_in,
                              void* d_out, int out_size)
{
    const float* X  = (const float*)d_in[0];
    const float* Wq = (const float*)d_in[1];
    const float* bq = (const float*)d_in[2];
    const float* Wk = (const float*)d_in[3];
    const float* bk = (const float*)d_in[4];
    const float* Wv = (const float*)d_in[5];
    const float* bv = (const float*)d_in[6];
    float* out = (float*)d_out;

    cudaFuncSetAttribute(qkv_tf32_kernel,
                         cudaFuncAttributeMaxDynamicSharedMemorySize, SMEM_BYTES);

    dim3 grid(24, 128);   // 24 n-blocks (8 per matrix), 128 m-blocks
    dim3 block(256);
    qkv_tf32_kernel<<<grid, block, SMEM_BYTES>>>(X, Wq, bq, Wk, bk, Wv, bv, out);
}

// round 3
// speedup vs baseline: 2.3944x; 2.3944x over previous
#include <cuda_runtime.h>
#include <cuda_fp16.h>
#include <cstdint>

// Fused QKV projection: X[16384,1024] @ [Wq|Wk|Wv][1024,3072] + bias,
// head-split epilogue. fp16 mma.sync.m16n8k16 (fp32 accum).
//
// Prep A: X -> fp16, permuted into m16n8k16 A-fragment order:
//   g_A[mtile(1024)][ktile(64)] : 32 lanes x 16B  (a0,a1,a2,a3 per lane)
// Prep B: W -> fp16, permuted into B-fragment order per 64-col block:
//   g_B[nblk64(48)][ktile(64)] : 4 chunks x 32 lanes x 16B
// GEMM: CTA 128x128, 8 warps (warp 32x64), BK=32, 4-stage cp.async.

#define MDIM 16384
#define KDIM 1024
#define NTOT 3072
#define BM 128
#define BN 128
#define BK 32
#define NKT (KDIM / BK)          // 32
#define NSTAGE 4
#define A_BYTES 8192             // 8 mtiles x 2 ktiles x 512B
#define B_BYTES 8192             // 2 nblk64 x 2 ktiles x 2048B
#define STAGE_BYTES (A_BYTES + B_BYTES)
#define SMEM_TOTAL (NSTAGE * STAGE_BYTES)   // 65536
#define OUT_PER_MAT (4 * 16 * 4096 * 64)

__device__ uint4 g_A[(size_t)1024 * 64 * 32];      // 32 MB
__device__ uint4 g_B[(size_t)48 * 64 * 4 * 32];    // 6 MB

__device__ __forceinline__ uint32_t h2u(float a, float b) {
    __half2 h = __float22half2_rn(make_float2(a, b));
    return *reinterpret_cast<uint32_t*>(&h);
}
__device__ __forceinline__ uint32_t smem_u32(const void* p) {
    uint32_t a;
    asm("{ .reg .u64 t; cvta.to.shared.u64 t, %1; cvt.u32.u64 %0, t; }" : "=r"(a) : "l"(p));
    return a;
}
__device__ __forceinline__ void cp16(uint32_t dst, const void* src) {
    asm volatile("cp.async.cg.shared.global [%0], [%1], 16;" :: "r"(dst), "l"(src));
}
__device__ __forceinline__ void mma_f16(float* c, const uint4& a, uint32_t b0, uint32_t b1) {
    asm volatile(
        "mma.sync.aligned.m16n8k16.row.col.f32.f16.f16.f32 "
        "{%0,%1,%2,%3},{%4,%5,%6,%7},{%8,%9},{%0,%1,%2,%3};"
        : "+f"(c[0]), "+f"(c[1]), "+f"(c[2]), "+f"(c[3])
        : "r"(a.x), "r"(a.y), "r"(a.z), "r"(a.w), "r"(b0), "r"(b1));
}

// ---------------- prep kernels ----------------
// A fragment (m16n8k16, row-major A 16x16): lane (g,t):
//   a0={A[g][2t],A[g][2t+1]} a1={A[g+8][2t],..} a2={A[g][2t+8],..} a3={A[g+8][2t+8],..}
__global__ void __launch_bounds__(256) prep_a(const float* __restrict__ X) {
    const int tId = blockIdx.x * 8 + (threadIdx.x >> 5);   // 65536 tiles
    const int lane = threadIdx.x & 31;
    const int g = lane >> 2, t = lane & 3;
    const int mt = tId >> 6, kt = tId & 63;
    const int r0 = mt * 16 + g;
    const int c0 = kt * 16 + 2 * t;
    const float2* x0 = reinterpret_cast<const float2*>(X + (size_t)r0 * KDIM + c0);
    const float2* x1 = reinterpret_cast<const float2*>(X + (size_t)(r0 + 8) * KDIM + c0);
    float2 v00 = x0[0], v02 = x0[4];
    float2 v10 = x1[0], v12 = x1[4];
    uint4 o;
    o.x = h2u(v00.x, v00.y);
    o.y = h2u(v10.x, v10.y);
    o.z = h2u(v02.x, v02.y);
    o.w = h2u(v12.x, v12.y);
    g_A[(size_t)tId * 32 + lane] = o;
}

// B fragment (k16 x n8, "col"): lane (g,t):
//   b0={B[2t][g],B[2t+1][g]}  b1={B[2t+8][g],B[2t+9][g]}
// chunk c packs ntiles 2c and 2c+1: {nt2c.b0, nt2c.b1, nt2c+1.b0, nt2c+1.b1}
__global__ void __launch_bounds__(256) prep_b(const float* __restrict__ Wq,
                                              const float* __restrict__ Wk,
                                              const float* __restrict__ Wv) {
    const int wId = blockIdx.x * 8 + (threadIdx.x >> 5);   // 12288 warps
    const int lane = threadIdx.x & 31;
    const int g = lane >> 2, t = lane & 3;
    const int nb = wId >> 8;          // 0..47
    const int kk = (wId >> 2) & 63;   // ktile16
    const int c = wId & 3;            // chunk
    const int n0 = nb * 64 + (2 * c) * 8 + g;
    const int n1 = n0 + 8;
    const float* W = (n0 < 1024) ? Wq : (n0 < 2048) ? Wk : Wv;
    const int nc0 = n0 & 1023, nc1 = n1 & 1023;
    const int k0 = kk * 16 + 2 * t;
    uint4 o;
    o.x = h2u(W[(size_t)k0 * 1024 + nc0],       W[(size_t)(k0 + 1) * 1024 + nc0]);
    o.y = h2u(W[(size_t)(k0 + 8) * 1024 + nc0], W[(size_t)(k0 + 9) * 1024 + nc0]);
    o.z = h2u(W[(size_t)k0 * 1024 + nc1],       W[(size_t)(k0 + 1) * 1024 + nc1]);
    o.w = h2u(W[(size_t)(k0 + 8) * 1024 + nc1], W[(size_t)(k0 + 9) * 1024 + nc1]);
    g_B[((size_t)(nb * 64 + kk) * 4 + c) * 32 + lane] = o;
}

// ---------------- GEMM ----------------
__global__ void __launch_bounds__(256, 2)
qkv_f16_mma(const float* __restrict__ bq, const float* __restrict__ bk,
            const float* __restrict__ bv, float* __restrict__ out) {
    extern __shared__ char smem[];
    const uint32_t sb = smem_u32(smem);
    const int tid = threadIdx.x;
    const int warp = tid >> 5;
    const int lane = tid & 31;
    const int g = lane >> 2, t = lane & 3;
    const int warpRow = warp >> 1;   // 0..3 (32 rows)
    const int warpCol = warp & 1;    // 0..1 (64 cols)

    const int nblk = blockIdx.x;         // 0..23
    const int mblk = blockIdx.y;         // 0..127
    const int mat = nblk >> 3;
    const int n0w = (nblk & 7) * BN;     // n within matrix
    const int m0 = mblk * BM;
    const int mtile0 = mblk * 8;
    const int nb0 = nblk * 2;            // global 64-col block index
    const float* bias = (mat == 0) ? bq : (mat == 1) ? bk : bv;

    float acc[2][8][4];
#pragma unroll
    for (int i = 0; i < 2; i++)
#pragma unroll
        for (int j = 0; j < 8; j++)
#pragma unroll
            for (int r = 0; r < 4; r++) acc[i][j][r] = 0.0f;

    auto load_stage = [&](int s, int kt) {
        const uint32_t aB = sb + s * STAGE_BYTES;
        const uint32_t bB = aB + A_BYTES;
#pragma unroll
        for (int i = 0; i < 2; i++) {   // A: 512 x 16B
            int chunk = tid + i * 256;
            int b = chunk >> 5, l = chunk & 31;
            int mt_i = b >> 1, kc = b & 1;
            cp16(aB + chunk * 16,
                 g_A + ((size_t)(mtile0 + mt_i) * 64 + kt * 2 + kc) * 32 + l);
        }
#pragma unroll
        for (int i = 0; i < 2; i++) {   // B: 512 x 16B
            int chunk = tid + i * 256;
            int b = chunk >> 7, inner = chunk & 127;
            int nb = b >> 1, kc = b & 1;
            cp16(bB + chunk * 16,
                 g_B + ((size_t)(nb0 + nb) * 64 + kt * 2 + kc) * 128 + inner);
        }
        asm volatile("cp.async.commit_group;" ::: "memory");
    };

    load_stage(0, 0);
    load_stage(1, 1);
    load_stage(2, 2);

    for (int kt = 0; kt < NKT; kt++) {
        const int s = kt & 3;
        if (kt + 3 < NKT) {
            load_stage((kt + 3) & 3, kt + 3);
            asm volatile("cp.async.wait_group 3;" ::: "memory");
        } else {
            asm volatile("cp.async.wait_group 0;" ::: "memory");
        }
        __syncthreads();

        const char* aP = smem + s * STAGE_BYTES;
        const char* bP = aP + A_BYTES;
#pragma unroll
        for (int kc = 0; kc < 2; kc++) {
            uint4 af[2];
#pragma unroll
            for (int mt = 0; mt < 2; mt++)
                af[mt] = *reinterpret_cast<const uint4*>(
                    aP + (((warpRow * 2 + mt) * 2 + kc) * 32 + lane) * 16);
            uint4 bf[4];
#pragma unroll
            for (int c = 0; c < 4; c++)
                bf[c] = *reinterpret_cast<const uint4*>(
                    bP + (((warpCol * 2 + kc) * 4 + c) * 32 + lane) * 16);
#pragma unroll
            for (int mt = 0; mt < 2; mt++)
#pragma unroll
                for (int nt = 0; nt < 8; nt++) {
                    const uint4& b = bf[nt >> 1];
                    uint32_t b0 = (nt & 1) ? b.z : b.x;
                    uint32_t b1 = (nt & 1) ? b.w : b.y;
                    mma_f16(acc[mt][nt], af[mt], b0, b1);
                }
        }
        __syncthreads();
    }

    // ---- epilogue: bias + head-split scatter ----
    float* outm = out + (size_t)mat * OUT_PER_MAT;
#pragma unroll
    for (int mt = 0; mt < 2; mt++) {
#pragma unroll
        for (int rh = 0; rh < 2; rh++) {
            const int row = m0 + warpRow * 32 + mt * 16 + g + rh * 8;
            const int bb = row >> 12;
            const int sq = row & 4095;
#pragma unroll
            for (int nt = 0; nt < 8; nt++) {
                const int nloc = n0w + warpCol * 64 + nt * 8 + 2 * t;
                const int head = nloc >> 6;
                const int d = nloc & 63;
                const float v0 = acc[mt][nt][rh * 2 + 0] + bias[nloc];
                const float v1 = acc[mt][nt][rh * 2 + 1] + bias[nloc + 1];
                const size_t idx = ((size_t)((bb * 16 + head) * 4096 + sq)) * 64 + d;
                *reinterpret_cast<float2*>(outm + idx) = make_float2(v0, v1);
            }
        }
    }
}

// ---------------- launch ----------------
extern "C" void kernel_launch(void* const* d_in, const int* in_sizes, int n_in,
                              void* d_out, int out_size) {
    const float* X  = (const float*)d_in[0];
    const float* Wq = (const float*)d_in[1];
    const float* bq = (const float*)d_in[2];
    const float* Wk = (const float*)d_in[3];
    const float* bk = (const float*)d_in[4];
    const float* Wv = (const float*)d_in[5];
    const float* bv = (const float*)d_in[6];
    float* out = (float*)d_out;

    prep_a<<<8192, 256>>>(X);
    prep_b<<<1536, 256>>>(Wq, Wk, Wv);

    cudaFuncSetAttribute(qkv_f16_mma,
                         cudaFuncAttributeMaxDynamicSharedMemorySize, SMEM_TOTAL);
    qkv_f16_mma<<<dim3(24, 128), 256, SMEM_TOTAL>>>(bq, bk, bv, out);
}